// round 11
// baseline (speedup 1.0000x reference)
#include <cuda_runtime.h>
#include <math.h>
#include <stdint.h>

#define B 32
#define L 64
#define E 512
#define H 1024
#define G4 4096
#define V 32000

typedef unsigned int u32;
typedef unsigned short u16;
typedef unsigned long long u64;

// ---------------- scratch state (device globals; no allocs) ----------------
__device__ float d_h[B*H];               // decoder h (fp32, for attn1)
__device__ float d_c[B*H];
__device__ u16   d_hbh[B*H];             // h as bf16 (GEMM A operand)
__device__ u16   d_cinbh[B*H];           // relu(combine) as bf16
__device__ float d_encouts[B*L*H];       // [b][l][j]
__device__ float d_xg[L][B][G4];         // precomputed emb@enc_wx + enc_b (orig gate order)
__device__ float d_gpart[8][B][G4];      // K-split partials (PERMUTED cols)
__device__ float d_cpart[8][B][H];       // K-split partials for combine GEMM
__device__ float d_ctx[B*H];             // attention context
__device__ float d_apart[8][B][64];      // attention logit partials
__device__ int   d_tok[B];
__device__ u32   d_owT[(size_t)V*512];   // out_w^T    [V][512]  bf16-pairs (64MB)
__device__ u32   d_whT[(size_t)G4*512];  // enc_wh^T   permuted [4096][512]  (8MB)
__device__ u32   d_gwT[(size_t)G4*1024]; // [dec_wx;dec_wh]^T permuted [4096][1024] (16MB)
__device__ u32   d_cwT[(size_t)H*1024];  // comb_w^T   [1024][1024] (4MB)
__device__ float d_lm2[B*250];           // per-(b,colchunk) max
__device__ float d_ls2[B*250];           // per-(b,colchunk) expsum
__device__ int   d_li2[B*250];           // per-(b,colchunk) argmax
__device__ float d_lseA[B*L];            // per-(b,t) log-sum-exp
__device__ int   d_ctr[64];              // last-block counters (self-resetting)

__device__ __forceinline__ float sigmoidf_(float x){ return 1.f/(1.f+expf(-x)); }
__device__ __forceinline__ u64 bcast_f(float x){ u64 r; asm("mov.b64 %0,{%1,%1};" : "=l"(r) : "f"(x)); return r; }
__device__ __forceinline__ void fma2(u64& d, u64 a, u64 b){ asm("fma.rn.f32x2 %0,%1,%2,%0;" : "+l"(d) : "l"(a), "l"(b)); }
__device__ __forceinline__ float lo_(u64 v){ return __uint_as_float((u32)v); }
__device__ __forceinline__ float hi_(u64 v){ return __uint_as_float((u32)(v>>32)); }
__device__ __forceinline__ u32 f2bf(float f){ u32 b=__float_as_uint(f); return (b + 0x7fffu + ((b>>16)&1u))>>16; }

// classic tensor-core mma (sm_80+, suffix-free PTX -> compiles for sm_103)
__device__ __forceinline__ void mma_bf16(float* d, u32 a0,u32 a1,u32 a2,u32 a3,u32 b0,u32 b1){
  asm volatile("mma.sync.aligned.m16n8k16.row.col.f32.bf16.bf16.f32 "
    "{%0,%1,%2,%3}, {%4,%5,%6,%7}, {%8,%9}, {%0,%1,%2,%3};"
    : "+f"(d[0]),"+f"(d[1]),"+f"(d[2]),"+f"(d[3])
    : "r"(a0),"r"(a1),"r"(a2),"r"(a3),"r"(b0),"r"(b1));
}

// online softmax-stat merge (max, expsum, argmax with first-index tie-break)
__device__ __forceinline__ void stat_merge(float& m, float& s, int& mi,
                                           float m2, float s2, int i2){
  if (m2 > m){ s = s*expf(m - m2) + s2; m = m2; mi = i2; }
  else { s += s2*expf(m2 - m); if (m2 == m && i2 < mi) mi = i2; }
}

// ---------------- init ----------------
__global__ void k_init(){
  int idx = blockIdx.x*256 + threadIdx.x;   // 32768 total
  d_h[idx]=0.f; d_c[idx]=0.f; d_hbh[idx]=0;
  if (idx < B) d_tok[idx] = 127;
  if (idx < 64) d_ctr[idx] = 0;
}

// ---------------- one-time generic transpose-convert ----------------
// src fp32 [K][N] (row stride ns) -> dst u32 [N'][kt] bf16-pairs at word offset k0w
// perm: gate-interleave columns: n' = (j/32)*128 + g*32 + (j%32), n = g*1024 + j
__global__ void k_T(const float* __restrict__ src, int ns, u32* __restrict__ dst,
                    int kt, int k0w, int nblks, int perm){
  __shared__ float sh[64][65];
  int nb = blockIdx.x % nblks, kb = blockIdx.x / nblks;
  int n0 = nb*64, k0 = kb*64;
  int tid = threadIdx.x;
  int nc = tid & 63, kg = tid >> 6;
  #pragma unroll
  for (int r=0;r<16;r++){
    int kr = kg*16 + r;
    sh[kr][nc] = src[(size_t)(k0+kr)*ns + n0 + nc];
  }
  __syncthreads();
  int nl = tid >> 2, p0 = (tid & 3)*8;
  int n = n0 + nl;
  int nrow = n;
  if (perm){
    int g = n >> 10, j = n & 1023;
    nrow = (j >> 5)*128 + g*32 + (j & 31);
  }
  u32* d = dst + (size_t)nrow*kt + k0w + (k0>>1);
  #pragma unroll
  for (int q=0;q<8;q++){
    int p = p0 + q;
    d[p] = (f2bf(sh[2*p+1][nl])<<16) | f2bf(sh[2*p][nl]);
  }
}

// ---------------- one-time: xg[t] = emb(x_t) @ enc_wx + enc_b ----------------
__global__ void k_xg(const int* __restrict__ x, const float* __restrict__ emb,
                     const float* __restrict__ wx, const float* __restrict__ eb){
  __shared__ float2 sh2[16][64];
  int tid = threadIdx.x;
  int t = blockIdx.x >> 5;
  int colbase = (blockIdx.x & 31)*128;
  int cl = tid & 63, bg = tid >> 6;
  u64 acc[2][4] = {};
  for (int kc=0;kc<8;kc++){
    int kb = kc*64;
    #pragma unroll
    for (int r=0;r<4;r++){
      int idx=tid+r*256; int bp=idx>>6, kk=idx&63; int k = kb+kk;
      sh2[bp][kk] = make_float2(emb[(size_t)x[(2*bp)*L+t]*E + k],
                                emb[(size_t)x[(2*bp+1)*L+t]*E + k]);
    }
    __syncthreads();
    #pragma unroll 8
    for (int kk=0;kk<64;kk++){
      float2 w = *(const float2*)(wx + (size_t)(kb+kk)*G4 + colbase + 2*cl);
      u64 wa = bcast_f(w.x), wb = bcast_f(w.y);
      #pragma unroll
      for (int bp=0;bp<4;bp++){
        u64 a = *(const u64*)&sh2[bg*4+bp][kk];
        fma2(acc[0][bp],a,wa); fma2(acc[1][bp],a,wb);
      }
    }
    __syncthreads();
  }
  int c0 = colbase + 2*cl;
  float e0 = eb[c0], e1 = eb[c0+1];
  #pragma unroll
  for (int bp=0;bp<4;bp++){
    int b0 = bg*8 + 2*bp;
    *(float2*)&d_xg[t][b0][c0]   = make_float2(lo_(acc[0][bp])+e0, lo_(acc[1][bp])+e1);
    *(float2*)&d_xg[t][b0+1][c0] = make_float2(hi_(acc[0][bp])+e0, hi_(acc[1][bp])+e1);
  }
}

// ---------------- generic bf16 mma GEMM with fused last-block epilogue ----------------
// mode 0: enc gates  A=hbh       wT=d_whT(perm) kt=512  chunks=1; epi: LSTM -> c,hbh,encouts
// mode 1: dec gates  A=cinbh|hbh wT=d_gwT(perm) kt=1024 chunks=2; epi: LSTM -> c,h,hbh
// mode 2: combine    A=e|ctx     wT=d_cwT       kt=1024 chunks=2; epi: reduce+bias+relu->cinbh
// grid = ncolblk*8 (ks = blockIdx.x & 7); 256 threads = 8 warps x 16 cols
__global__ void k_mm_bf16(int mode, const float* __restrict__ demb,
                          const float* __restrict__ bias, int t){
  __shared__ u32 sA[32][68];
  __shared__ float sO[32][132];
  __shared__ int sLast;
  int tid = threadIdx.x, wid = tid>>5, lane = tid&31;
  int ks = blockIdx.x & 7;
  int colblk = blockIdx.x >> 3;
  int colbase = colblk*128;
  int g = lane>>2, q = lane&3;
  const u32* wT; int kt, chunks; float* outp; int ostride;
  if (mode == 0){ wT = d_whT; kt = 512;  chunks = 1; outp = &d_gpart[0][0][0]; ostride = G4; }
  else if (mode == 1){ wT = d_gwT; kt = 1024; chunks = 2; outp = &d_gpart[0][0][0]; ostride = G4; }
  else { wT = d_cwT; kt = 1024; chunks = 2; outp = &d_cpart[0][0][0]; ostride = H; }

  float acc[2][2][4] = {};
  const u32* wp = wT + (size_t)(colbase + wid*16 + g)*kt + q;

  for (int kc=0; kc<chunks; kc++){
    int kb = (ks*chunks + kc)*128;
    {
      int row = tid>>3, w0 = (tid&7)*8;
      if (mode == 0){
        const uint4* hp = (const uint4*)(d_hbh + row*H + kb + w0*2);
        *(uint4*)&sA[row][w0]   = hp[0];
        *(uint4*)&sA[row][w0+4] = hp[1];
      } else if (mode == 1){
        const u16* src = (kb < H) ? (d_cinbh + row*H + kb) : (d_hbh + row*H + kb - H);
        const uint4* hp = (const uint4*)(src + w0*2);
        *(uint4*)&sA[row][w0]   = hp[0];
        *(uint4*)&sA[row][w0+4] = hp[1];
      } else {
        if (kb < H){
          int tok = d_tok[row];
          const float2* ep = (const float2*)(demb + (size_t)tok*H + kb);
          #pragma unroll
          for (int i=0;i<8;i++){
            float2 v = ep[w0+i];
            sA[row][w0+i] = (f2bf(v.y)<<16) | f2bf(v.x);
          }
        } else {
          const float2* cp = (const float2*)(d_ctx + row*H + (kb-H));
          #pragma unroll
          for (int i=0;i<8;i++){
            float2 v = cp[w0+i];
            sA[row][w0+i] = (f2bf(v.y)<<16) | f2bf(v.x);
          }
        }
      }
    }
    __syncthreads();
    const u32* wkc = wp + (ks*chunks + kc)*64;
    #pragma unroll
    for (int kss=0;kss<8;kss++){
      int kw = kss*8;
      u32 a00 = sA[g   ][kw+q],   a10 = sA[g+8 ][kw+q];
      u32 a20 = sA[g   ][kw+4+q], a30 = sA[g+8 ][kw+4+q];
      u32 a01 = sA[g+16][kw+q],   a11 = sA[g+24][kw+q];
      u32 a21 = sA[g+16][kw+4+q], a31 = sA[g+24][kw+4+q];
      #pragma unroll
      for (int j=0;j<2;j++){
        u32 b0 = wkc[(size_t)j*8*kt + kw];
        u32 b1 = wkc[(size_t)j*8*kt + kw + 4];
        mma_bf16(acc[0][j], a00,a10,a20,a30, b0,b1);
        mma_bf16(acc[1][j], a01,a11,a21,a31, b0,b1);
      }
    }
    __syncthreads();
  }
  #pragma unroll
  for (int m=0;m<2;m++)
    #pragma unroll
    for (int j=0;j<2;j++){
      int col = wid*16 + j*8 + q*2;
      *(float2*)&sO[g + m*16    ][col] = make_float2(acc[m][j][0], acc[m][j][1]);
      *(float2*)&sO[g + m*16 + 8][col] = make_float2(acc[m][j][2], acc[m][j][3]);
    }
  __syncthreads();
  #pragma unroll
  for (int rr=0;rr<4;rr++){
    int b = wid*4 + rr;
    int c0 = lane*4;
    float4 v = *(float4*)&sO[b][c0];
    *(float4*)(outp + (size_t)(ks*B + b)*ostride + colbase + c0) = v;
  }

  // ---- last-block fused epilogue ----
  __threadfence();
  __syncthreads();
  if (tid == 0){
    int ci = (mode == 2) ? 32 + colblk : colblk;
    int old = atomicAdd(&d_ctr[ci], 1);
    sLast = (old == 7);
    if (old == 7) d_ctr[ci] = 0;
  }
  __syncthreads();
  if (!sLast) return;
  __threadfence();
  if (mode == 2){
    // reduce + bias + relu -> cinbh for cols [colbase, colbase+128)
    for (int i=tid; i<4096; i+=256){
      int b = i>>7, jj = i&127; int j = colbase + jj;
      float s = bias[j];
      #pragma unroll
      for (int p=0;p<8;p++) s += d_cpart[p][b][j];
      d_cinbh[b*H + j] = (u16)f2bf(fmaxf(s, 0.f));
    }
  } else {
    // LSTM pointwise for j in [colblk*32, +32): all 4 gates live in this colblk (permuted)
    for (int i=tid; i<1024; i+=256){
      int b = i>>5, jj = i&31; int j = colblk*32 + jj;
      float gv[4];
      #pragma unroll
      for (int gg=0; gg<4; gg++){
        int nP = colbase + gg*32 + jj;
        float s = (mode == 0) ? d_xg[t][b][gg*1024 + j] : bias[gg*1024 + j];
        #pragma unroll
        for (int p=0;p<8;p++) s += d_gpart[p][b][nP];
        gv[gg] = s;
      }
      float c = d_c[b*H + j];
      c = sigmoidf_(gv[1])*c + sigmoidf_(gv[0])*tanhf(gv[2]);
      float h = sigmoidf_(gv[3])*tanhf(c);
      d_c[b*H + j] = c;
      d_hbh[b*H + j] = (u16)f2bf(h);
      if (mode == 0) d_encouts[(b*L + t)*H + j] = h;
      else d_h[b*H + j] = h;
    }
  }
}

// ---------------- attention phase 1: logit partials ----------------
// grid 256 = 32 b x 8 ks (256 K each)
__global__ void k_attn1(const float* __restrict__ demb, const float* __restrict__ aw_w){
  __shared__ float sp[256];
  int b = blockIdx.x >> 3, ks = blockIdx.x & 7;
  int tid = threadIdx.x;
  int tok = d_tok[b];
  const float* erow = demb + (size_t)tok*H;
  int col = tid & 63, kg = tid >> 6;
  int k0 = ks*256 + kg*64;
  float acc = 0.f;
  const float* arow = (k0 < H) ? (erow + k0) : (d_h + b*H + (k0-H));
  #pragma unroll 4
  for (int i=0;i<64;i++) acc += arow[i] * aw_w[(size_t)(k0+i)*64 + col];
  sp[tid] = acc;
  __syncthreads();
  if (tid < 64) d_apart[ks][b][tid] = sp[tid] + sp[tid+64] + sp[tid+128] + sp[tid+192];
}

// ---------------- attention phase 2: softmax + context ----------------
// grid 128 = 32 b x 4 jblk (256 j each)
__global__ void k_attn_ctx(const float* __restrict__ ab){
  __shared__ float s_aw[64];
  __shared__ float s_red[2];
  int b = blockIdx.x >> 2, jblk = blockIdx.x & 3;
  int tid = threadIdx.x;
  if (tid < 64){
    float lg = ab[tid];
    #pragma unroll
    for (int p=0;p<8;p++) lg += d_apart[p][b][tid];
    s_aw[tid] = lg;
  }
  __syncthreads();
  if (tid < 32){
    float m = fmaxf(s_aw[tid], s_aw[tid+32]);
    #pragma unroll
    for (int o=16;o>0;o>>=1) m = fmaxf(m, __shfl_xor_sync(0xffffffffu, m, o));
    if (tid==0) s_red[0]=m;
  }
  __syncthreads();
  if (tid < 64) s_aw[tid] = expf(s_aw[tid] - s_red[0]);
  __syncthreads();
  if (tid < 32){
    float s = s_aw[tid] + s_aw[tid+32];
    #pragma unroll
    for (int o=16;o>0;o>>=1) s += __shfl_xor_sync(0xffffffffu, s, o);
    if (tid==0) s_red[1]=s;
  }
  __syncthreads();
  float inv = 1.f / s_red[1];
  int j = jblk*256 + tid;
  float c = 0.f;
  #pragma unroll 4
  for (int l=0;l<64;l++) c += s_aw[l]*inv * d_encouts[(b*L + l)*H + j];
  d_ctx[b*H + j] = c;
}

// ---------------- logits via mma.sync bf16 + fused token/lse reduction ----------------
// grid 250 (128 vocab cols each); 256 threads = 8 warps (warp w: cols w*16..w*16+15)
__global__ void k_logits_mma(const float* __restrict__ ob, float* __restrict__ out, int t){
  __shared__ u32 sA[32][68];
  __shared__ float sLg[32][132];
  __shared__ int sLast;
  int tid = threadIdx.x, wid = tid>>5, lane = tid&31;
  int colbase = blockIdx.x*128;
  int g = lane>>2, q = lane&3;
  float acc[2][2][4];
  #pragma unroll
  for (int m=0;m<2;m++)
    #pragma unroll
    for (int j=0;j<2;j++)
      #pragma unroll
      for (int r=0;r<4;r++) acc[m][j][r]=0.f;

  const u32* wp = d_owT + (size_t)(colbase + wid*16 + g)*512 + q;

  for (int kc=0;kc<8;kc++){
    {
      int row = tid>>3, w0 = (tid&7)*8;
      const uint4* hp = (const uint4*)(d_hbh + row*H + kc*128 + w0*2);
      *(uint4*)&sA[row][w0]   = hp[0];
      *(uint4*)&sA[row][w0+4] = hp[1];
    }
    __syncthreads();
    const u32* wkc = wp + kc*64;
    #pragma unroll
    for (int ks=0;ks<8;ks++){
      int kw = ks*8;
      u32 a00 = sA[g   ][kw+q], a10 = sA[g+8 ][kw+q];
      u32 a20 = sA[g   ][kw+4+q], a30 = sA[g+8 ][kw+4+q];
      u32 a01 = sA[g+16][kw+q], a11 = sA[g+24][kw+q];
      u32 a21 = sA[g+16][kw+4+q], a31 = sA[g+24][kw+4+q];
      #pragma unroll
      for (int j=0;j<2;j++){
        u32 b0 = wkc[j*8*512 + kw];
        u32 b1 = wkc[j*8*512 + kw + 4];
        mma_bf16(acc[0][j], a00,a10,a20,a30, b0,b1);
        mma_bf16(acc[1][j], a01,a11,a21,a31, b0,b1);
      }
    }
    __syncthreads();
  }
  #pragma unroll
  for (int m=0;m<2;m++)
    #pragma unroll
    for (int j=0;j<2;j++){
      int col = wid*16 + j*8 + q*2;
      *(float2*)&sLg[g + m*16    ][col] = make_float2(acc[m][j][0], acc[m][j][1]);
      *(float2*)&sLg[g + m*16 + 8][col] = make_float2(acc[m][j][2], acc[m][j][3]);
    }
  __syncthreads();
  const float* bp = ob + colbase;
  float4 bb = *(const float4*)(bp + lane*4);
  #pragma unroll
  for (int rr=0;rr<4;rr++){
    int b = wid*4 + rr;
    int c0 = lane*4;
    float4 v = *(float4*)&sLg[b][c0];
    v.x += bb.x; v.y += bb.y; v.z += bb.z; v.w += bb.w;
    float* orow = out + ((size_t)(b*L + t))*V + colbase;
    *(float4*)(orow + c0) = v;
    float m = v.x; int mi = c0;
    if (v.y > m){ m=v.y; mi=c0+1; }
    if (v.z > m){ m=v.z; mi=c0+2; }
    if (v.w > m){ m=v.w; mi=c0+3; }
    #pragma unroll
    for (int o=16;o>0;o>>=1){
      float om = __shfl_xor_sync(0xffffffffu, m, o);
      int   oi = __shfl_xor_sync(0xffffffffu, mi, o);
      if (om > m || (om == m && oi < mi)){ m=om; mi=oi; }
    }
    float S = expf(v.x-m)+expf(v.y-m)+expf(v.z-m)+expf(v.w-m);
    #pragma unroll
    for (int o=16;o>0;o>>=1) S += __shfl_xor_sync(0xffffffffu, S, o);
    if (lane == 0){
      d_lm2[b*250 + blockIdx.x] = m;
      d_ls2[b*250 + blockIdx.x] = S;
      d_li2[b*250 + blockIdx.x] = colbase + mi;
    }
  }

  // ---- global last-block: merge 250 chunk stats -> token + lse ----
  __threadfence();
  __syncthreads();
  if (tid == 0){
    int old = atomicAdd(&d_ctr[40], 1);
    sLast = (old == 249);
    if (old == 249) d_ctr[40] = 0;
  }
  __syncthreads();
  if (!sLast) return;
  __threadfence();
  #pragma unroll
  for (int rr=0; rr<4; rr++){
    int b = wid + rr*8;                 // 8 warps x 4 = 32 rows
    float m = -INFINITY, s = 0.f; int mi = 0x7fffffff;
    for (int c = lane; c < 250; c += 32)
      stat_merge(m, s, mi, d_lm2[b*250+c], d_ls2[b*250+c], d_li2[b*250+c]);
    #pragma unroll
    for (int o=16;o>0;o>>=1){
      float m2 = __shfl_xor_sync(0xffffffffu, m, o);
      float s2 = __shfl_xor_sync(0xffffffffu, s, o);
      int   i2 = __shfl_xor_sync(0xffffffffu, mi, o);
      stat_merge(m, s, mi, m2, s2, i2);
    }
    if (lane == 0){
      d_tok[b] = mi;
      d_lseA[b*L + t] = m + logf(s);
    }
  }
}

// ---------------- final: subtract lse from every logit row ----------------
// grid 2048 (one block per (b,t) row)
__global__ void k_sub(float* __restrict__ out){
  int row = blockIdx.x;
  float lse = d_lseA[row];
  float4* p = (float4*)(out + (size_t)row*V);
  for (int i = threadIdx.x; i < V/4; i += 256){
    float4 v = p[i];
    v.x -= lse; v.y -= lse; v.z -= lse; v.w -= lse;
    p[i] = v;
  }
}

// ---------------- launcher ----------------
extern "C" void kernel_launch(void* const* d_in, const int* in_sizes, int n_in,
                              void* d_out, int out_size){
  const int*   x         = (const int*)  d_in[0];
  const float* enc_embed = (const float*)d_in[1];
  const float* enc_wx    = (const float*)d_in[2];
  const float* enc_wh    = (const float*)d_in[3];
  const float* enc_b     = (const float*)d_in[4];
  const float* dec_embed = (const float*)d_in[5];
  const float* attn_w    = (const float*)d_in[6];
  const float* attn_b    = (const float*)d_in[7];
  const float* comb_w    = (const float*)d_in[8];
  const float* comb_b    = (const float*)d_in[9];
  const float* dec_wx    = (const float*)d_in[10];
  const float* dec_wh    = (const float*)d_in[11];
  const float* dec_b     = (const float*)d_in[12];
  const float* out_w     = (const float*)d_in[13];
  const float* out_b     = (const float*)d_in[14];
  float* out = (float*)d_out;

  u32 *p_owT, *p_whT, *p_gwT, *p_cwT;
  cudaGetSymbolAddress((void**)&p_owT, d_owT);
  cudaGetSymbolAddress((void**)&p_whT, d_whT);
  cudaGetSymbolAddress((void**)&p_gwT, d_gwT);
  cudaGetSymbolAddress((void**)&p_cwT, d_cwT);

  k_init<<<128,256>>>();
  k_T<<<500*16,256>>>(out_w,   V,  p_owT, 512,  0,   500, 0);  // out_w^T
  k_T<<<64*16, 256>>>(enc_wh,  G4, p_whT, 512,  0,   64,  1);  // enc_wh^T (gate-perm)
  k_T<<<64*16, 256>>>(dec_wx,  G4, p_gwT, 1024, 0,   64,  1);  // dec_wx^T (gate-perm)
  k_T<<<64*16, 256>>>(dec_wh,  G4, p_gwT, 1024, 512, 64,  1);  // dec_wh^T (gate-perm)
  k_T<<<16*32, 256>>>(comb_w,  H,  p_cwT, 1024, 0,   16,  0);  // comb_w^T
  k_xg<<<2048,256>>>(x, enc_embed, enc_wx, enc_b);
  for (int t=0;t<64;t++)
    k_mm_bf16<<<256,256>>>(0, nullptr, nullptr, t);   // gates GEMM + fused LSTM epilogue
  k_init<<<128,256>>>();
  for (int t=0;t<64;t++){
    k_attn1<<<256,256>>>(dec_embed, attn_w);
    k_attn_ctx<<<128,256>>>(attn_b);
    k_mm_bf16<<<64,256>>>(2, dec_embed, comb_b, 0);   // combine + fused relu epilogue
    k_mm_bf16<<<256,256>>>(1, nullptr, dec_b, 0);     // gates + fused LSTM epilogue
    k_logits_mma<<<250,256>>>(out_b, out, t);         // logits + fused token/lse
  }
  k_sub<<<2048,256>>>(out);
}

// round 12
// speedup vs baseline: 1.3543x; 1.3543x over previous
#include <cuda_runtime.h>
#include <math.h>
#include <stdint.h>

#define B 32
#define L 64
#define E 512
#define H 1024
#define G4 4096
#define V 32000

typedef unsigned int u32;
typedef unsigned short u16;
typedef unsigned long long u64;

// ---------------- scratch state (device globals; no allocs) ----------------
__device__ float d_h[B*H];               // decoder h (fp32, for attn1)
__device__ float d_c[B*H];
__device__ u16   d_hbh[B*H];             // h as bf16 (GEMM A operand)
__device__ u16   d_cinbh[B*H];           // relu(combine) as bf16
__device__ float d_encouts[B*L*H];       // [b][l][j]
__device__ float d_xg[L][B][G4];         // precomputed emb@enc_wx + enc_b
__device__ float d_gpart[8][B][G4];      // K-split partials for gate GEMMs
__device__ float d_cpart[8][B][H];       // K-split partials for combine GEMM
__device__ float d_ctx[B*H];             // attention context
__device__ float d_apart[8][B][64];      // attention logit partials
__device__ int   d_tok[B];
__device__ u32   d_owT[(size_t)V*512];   // out_w^T    [V][512]  bf16-pairs (64MB)
__device__ u32   d_whT[(size_t)G4*512];  // enc_wh^T   [4096][512]  (8MB)
__device__ u32   d_gwT[(size_t)G4*1024]; // [dec_wx;dec_wh]^T [4096][1024] (16MB)
__device__ u32   d_cwT[(size_t)H*1024];  // comb_w^T   [1024][1024] (4MB)
__device__ u32   d_xwT[(size_t)G4*256];  // enc_wx^T   [4096][256]  (4MB)
__device__ float d_lm2[B*250];           // per-(b,colchunk) max
__device__ float d_ls2[B*250];           // per-(b,colchunk) expsum
__device__ int   d_li2[B*250];           // per-(b,colchunk) argmax
__device__ float d_lseA[B*L];            // per-(b,t) log-sum-exp

__device__ __forceinline__ float sigmoidf_(float x){ return 1.f/(1.f+expf(-x)); }
__device__ __forceinline__ u32 f2bf(float f){ u32 b=__float_as_uint(f); return (b + 0x7fffu + ((b>>16)&1u))>>16; }

// classic tensor-core mma (sm_80+, suffix-free PTX -> compiles for sm_103)
__device__ __forceinline__ void mma_bf16(float* d, u32 a0,u32 a1,u32 a2,u32 a3,u32 b0,u32 b1){
  asm volatile("mma.sync.aligned.m16n8k16.row.col.f32.bf16.bf16.f32 "
    "{%0,%1,%2,%3}, {%4,%5,%6,%7}, {%8,%9}, {%0,%1,%2,%3};"
    : "+f"(d[0]),"+f"(d[1]),"+f"(d[2]),"+f"(d[3])
    : "r"(a0),"r"(a1),"r"(a2),"r"(a3),"r"(b0),"r"(b1));
}

// ---------------- init ----------------
__global__ void k_init(){
  int idx = blockIdx.x*256 + threadIdx.x;   // 32768 total
  d_h[idx]=0.f; d_c[idx]=0.f; d_hbh[idx]=0;
  if (idx < B) d_tok[idx] = 127;
}

// ---------------- one-time generic transpose-convert ----------------
// src fp32 [K][N] (row stride ns) -> dst u32 [N][kt] bf16-pairs at word offset k0w
__global__ void k_T(const float* __restrict__ src, int ns, u32* __restrict__ dst,
                    int kt, int k0w, int nblks){
  __shared__ float sh[64][65];
  int nb = blockIdx.x % nblks, kb = blockIdx.x / nblks;
  int n0 = nb*64, k0 = kb*64;
  int tid = threadIdx.x;
  int nc = tid & 63, kg = tid >> 6;
  #pragma unroll
  for (int r=0;r<16;r++){
    int kr = kg*16 + r;
    sh[kr][nc] = src[(size_t)(k0+kr)*ns + n0 + nc];
  }
  __syncthreads();
  int nl = tid >> 2, p0 = (tid & 3)*8;
  u32* d = dst + (size_t)(n0+nl)*kt + k0w + (k0>>1);
  #pragma unroll
  for (int q=0;q<8;q++){
    int p = p0 + q;
    d[p] = (f2bf(sh[2*p+1][nl])<<16) | f2bf(sh[2*p][nl]);
  }
}

// ---------------- one-time: xg[t] = emb(x_t) @ enc_wx + enc_b (bf16 mma) ----------------
// grid 2048 = 64 t x 32 colblk(128); 256 threads = 8 warps x 16 cols; K=512 in 4 chunks
__global__ void k_xg_mma(const int* __restrict__ x, const float* __restrict__ emb,
                         const float* __restrict__ eb){
  __shared__ u32 sA[32][68];
  __shared__ float sO[32][132];
  int tid = threadIdx.x, wid = tid>>5, lane = tid&31;
  int t = blockIdx.x >> 5;
  int colbase = (blockIdx.x & 31)*128;
  int g = lane>>2, q = lane&3;
  float acc[2][2][4] = {};
  const u32* wp = d_xwT + (size_t)(colbase + wid*16 + g)*256 + q;

  for (int kc=0;kc<4;kc++){
    int kb = kc*128;
    {
      int row = tid>>3, w0 = (tid&7)*8;
      int tok = x[row*L + t];
      const float2* ep = (const float2*)(emb + (size_t)tok*E + kb) + w0;
      #pragma unroll
      for (int i=0;i<8;i++){
        float2 v = ep[i];
        sA[row][w0+i] = (f2bf(v.y)<<16) | f2bf(v.x);
      }
    }
    __syncthreads();
    const u32* wkc = wp + kc*64;
    #pragma unroll
    for (int kss=0;kss<8;kss++){
      int kw = kss*8;
      u32 a00 = sA[g   ][kw+q],   a10 = sA[g+8 ][kw+q];
      u32 a20 = sA[g   ][kw+4+q], a30 = sA[g+8 ][kw+4+q];
      u32 a01 = sA[g+16][kw+q],   a11 = sA[g+24][kw+q];
      u32 a21 = sA[g+16][kw+4+q], a31 = sA[g+24][kw+4+q];
      #pragma unroll
      for (int j=0;j<2;j++){
        u32 b0 = wkc[j*8*256 + kw];
        u32 b1 = wkc[j*8*256 + kw + 4];
        mma_bf16(acc[0][j], a00,a10,a20,a30, b0,b1);
        mma_bf16(acc[1][j], a01,a11,a21,a31, b0,b1);
      }
    }
    __syncthreads();
  }
  #pragma unroll
  for (int m=0;m<2;m++)
    #pragma unroll
    for (int j=0;j<2;j++){
      int col = wid*16 + j*8 + q*2;
      *(float2*)&sO[g + m*16    ][col] = make_float2(acc[m][j][0], acc[m][j][1]);
      *(float2*)&sO[g + m*16 + 8][col] = make_float2(acc[m][j][2], acc[m][j][3]);
    }
  __syncthreads();
  int c0 = lane*4;
  float4 bb = *(const float4*)(eb + colbase + c0);
  #pragma unroll
  for (int rr=0;rr<4;rr++){
    int b = wid*4 + rr;
    float4 v = *(float4*)&sO[b][c0];
    v.x += bb.x; v.y += bb.y; v.z += bb.z; v.w += bb.w;
    *(float4*)&d_xg[t][b][colbase + c0] = v;
  }
}

// ---------------- generic bf16 mma GEMM: P[32 x 128cols] partials ----------------
// mode 0: enc gates  A=hbh          wT=d_whT kt=512  chunks=1 out=d_gpart stride G4
// mode 1: dec gates  A=cinbh|hbh    wT=d_gwT kt=1024 chunks=2 out=d_gpart stride G4
// mode 2: combine    A=e|ctx        wT=d_cwT kt=1024 chunks=2 out=d_cpart stride H
// grid = ncolblk*8 (ks = blockIdx.x & 7); 256 threads = 8 warps x 16 cols
__global__ void k_mm_bf16(int mode, const float* __restrict__ demb){
  __shared__ u32 sA[32][68];
  __shared__ float sO[32][132];
  int tid = threadIdx.x, wid = tid>>5, lane = tid&31;
  int ks = blockIdx.x & 7;
  int colbase = (blockIdx.x >> 3)*128;
  int g = lane>>2, q = lane&3;
  const u32* wT; int kt, chunks; float* outp; int ostride;
  if (mode == 0){ wT = d_whT; kt = 512;  chunks = 1; outp = &d_gpart[0][0][0]; ostride = G4; }
  else if (mode == 1){ wT = d_gwT; kt = 1024; chunks = 2; outp = &d_gpart[0][0][0]; ostride = G4; }
  else { wT = d_cwT; kt = 1024; chunks = 2; outp = &d_cpart[0][0][0]; ostride = H; }

  float acc[2][2][4] = {};
  const u32* wp = wT + (size_t)(colbase + wid*16 + g)*kt + q;

  for (int kc=0; kc<chunks; kc++){
    int kb = (ks*chunks + kc)*128;
    {
      int row = tid>>3, w0 = (tid&7)*8;
      if (mode == 0){
        const uint4* hp = (const uint4*)(d_hbh + row*H + kb + w0*2);
        *(uint4*)&sA[row][w0]   = hp[0];
        *(uint4*)&sA[row][w0+4] = hp[1];
      } else if (mode == 1){
        const u16* src = (kb < H) ? (d_cinbh + row*H + kb) : (d_hbh + row*H + kb - H);
        const uint4* hp = (const uint4*)(src + w0*2);
        *(uint4*)&sA[row][w0]   = hp[0];
        *(uint4*)&sA[row][w0+4] = hp[1];
      } else {
        if (kb < H){
          int tok = d_tok[row];
          const float2* ep = (const float2*)(demb + (size_t)tok*H + kb);
          #pragma unroll
          for (int i=0;i<8;i++){
            float2 v = ep[w0+i];
            sA[row][w0+i] = (f2bf(v.y)<<16) | f2bf(v.x);
          }
        } else {
          const float2* cp = (const float2*)(d_ctx + row*H + (kb-H));
          #pragma unroll
          for (int i=0;i<8;i++){
            float2 v = cp[w0+i];
            sA[row][w0+i] = (f2bf(v.y)<<16) | f2bf(v.x);
          }
        }
      }
    }
    __syncthreads();
    const u32* wkc = wp + (ks*chunks + kc)*64;
    #pragma unroll
    for (int kss=0;kss<8;kss++){
      int kw = kss*8;
      u32 a00 = sA[g   ][kw+q],   a10 = sA[g+8 ][kw+q];
      u32 a20 = sA[g   ][kw+4+q], a30 = sA[g+8 ][kw+4+q];
      u32 a01 = sA[g+16][kw+q],   a11 = sA[g+24][kw+q];
      u32 a21 = sA[g+16][kw+4+q], a31 = sA[g+24][kw+4+q];
      #pragma unroll
      for (int j=0;j<2;j++){
        u32 b0 = wkc[(size_t)j*8*kt + kw];
        u32 b1 = wkc[(size_t)j*8*kt + kw + 4];
        mma_bf16(acc[0][j], a00,a10,a20,a30, b0,b1);
        mma_bf16(acc[1][j], a01,a11,a21,a31, b0,b1);
      }
    }
    __syncthreads();
  }
  #pragma unroll
  for (int m=0;m<2;m++)
    #pragma unroll
    for (int j=0;j<2;j++){
      int col = wid*16 + j*8 + q*2;
      *(float2*)&sO[g + m*16    ][col] = make_float2(acc[m][j][0], acc[m][j][1]);
      *(float2*)&sO[g + m*16 + 8][col] = make_float2(acc[m][j][2], acc[m][j][3]);
    }
  __syncthreads();
  #pragma unroll
  for (int rr=0;rr<4;rr++){
    int b = wid*4 + rr;
    int c0 = lane*4;
    float4 v = *(float4*)&sO[b][c0];
    *(float4*)(outp + (size_t)(ks*B + b)*ostride + colbase + c0) = v;
  }
}

// ---------------- encoder pointwise ----------------
__global__ void k_enc_point(int t){
  int idx = blockIdx.x*256 + threadIdx.x;
  int b = idx >> 10, j = idx & 1023;
  float g0 = d_xg[t][b][j],      g1 = d_xg[t][b][j+1024];
  float g2 = d_xg[t][b][j+2048], g3 = d_xg[t][b][j+3072];
  #pragma unroll
  for (int p=0;p<8;p++){
    g0 += d_gpart[p][b][j];      g1 += d_gpart[p][b][j+1024];
    g2 += d_gpart[p][b][j+2048]; g3 += d_gpart[p][b][j+3072];
  }
  float c = d_c[idx];
  c = sigmoidf_(g1)*c + sigmoidf_(g0)*tanhf(g2);
  float h = sigmoidf_(g3)*tanhf(c);
  d_c[idx]=c;
  d_hbh[idx] = (u16)f2bf(h);
  d_encouts[(b*L + t)*H + j] = h;
}

// ---------------- attention phase 1: logit partials ----------------
// grid 256 = 32 b x 8 ks (256 K each)
__global__ void k_attn1(const float* __restrict__ demb, const float* __restrict__ aw_w){
  __shared__ float sp[256];
  int b = blockIdx.x >> 3, ks = blockIdx.x & 7;
  int tid = threadIdx.x;
  int tok = d_tok[b];
  const float* erow = demb + (size_t)tok*H;
  int col = tid & 63, kg = tid >> 6;
  int k0 = ks*256 + kg*64;
  float acc = 0.f;
  const float* arow = (k0 < H) ? (erow + k0) : (d_h + b*H + (k0-H));
  #pragma unroll 4
  for (int i=0;i<64;i++) acc += arow[i] * aw_w[(size_t)(k0+i)*64 + col];
  sp[tid] = acc;
  __syncthreads();
  if (tid < 64) d_apart[ks][b][tid] = sp[tid] + sp[tid+64] + sp[tid+128] + sp[tid+192];
}

// ---------------- attention phase 2: softmax + context ----------------
// grid 128 = 32 b x 4 jblk (256 j each)
__global__ void k_attn_ctx(const float* __restrict__ ab){
  __shared__ float s_aw[64];
  __shared__ float s_red[2];
  int b = blockIdx.x >> 2, jblk = blockIdx.x & 3;
  int tid = threadIdx.x;
  if (tid < 64){
    float lg = ab[tid];
    #pragma unroll
    for (int p=0;p<8;p++) lg += d_apart[p][b][tid];
    s_aw[tid] = lg;
  }
  __syncthreads();
  if (tid < 32){
    float m = fmaxf(s_aw[tid], s_aw[tid+32]);
    #pragma unroll
    for (int o=16;o>0;o>>=1) m = fmaxf(m, __shfl_xor_sync(0xffffffffu, m, o));
    if (tid==0) s_red[0]=m;
  }
  __syncthreads();
  if (tid < 64) s_aw[tid] = expf(s_aw[tid] - s_red[0]);
  __syncthreads();
  if (tid < 32){
    float s = s_aw[tid] + s_aw[tid+32];
    #pragma unroll
    for (int o=16;o>0;o>>=1) s += __shfl_xor_sync(0xffffffffu, s, o);
    if (tid==0) s_red[1]=s;
  }
  __syncthreads();
  float inv = 1.f / s_red[1];
  int j = jblk*256 + tid;
  float c = 0.f;
  #pragma unroll 4
  for (int l=0;l<64;l++) c += s_aw[l]*inv * d_encouts[(b*L + l)*H + j];
  d_ctx[b*H + j] = c;
}

// ---------------- combine finalize: reduce + bias + relu -> bf16 ----------------
__global__ void k_combfin(const float* __restrict__ cb){
  int idx = blockIdx.x*256 + threadIdx.x;
  int b = idx >> 10, j = idx & 1023;
  float s = cb[j];
  #pragma unroll
  for (int p=0;p<8;p++) s += d_cpart[p][b][j];
  d_cinbh[idx] = (u16)f2bf(fmaxf(s, 0.f));
}

// ---------------- decoder pointwise ----------------
__global__ void k_dec_point(const float* __restrict__ db){
  int idx = blockIdx.x*256 + threadIdx.x;
  int b = idx >> 10, j = idx & 1023;
  float g0 = db[j], g1 = db[j+1024], g2 = db[j+2048], g3 = db[j+3072];
  #pragma unroll
  for (int p=0;p<8;p++){
    g0 += d_gpart[p][b][j];      g1 += d_gpart[p][b][j+1024];
    g2 += d_gpart[p][b][j+2048]; g3 += d_gpart[p][b][j+3072];
  }
  float c = d_c[idx];
  c = sigmoidf_(g1)*c + sigmoidf_(g0)*tanhf(g2);
  float h = sigmoidf_(g3)*tanhf(c);
  d_c[idx]=c; d_h[idx]=h;
  d_hbh[idx] = (u16)f2bf(h);
}

// ---------------- logits via mma.sync bf16: D[32 x 128] per block ----------------
// grid 250 (128 vocab cols each); 256 threads = 8 warps (warp w: cols w*16..w*16+15)
__global__ void k_logits_mma(const float* __restrict__ ob, float* __restrict__ out, int t){
  __shared__ u32 sA[32][68];
  __shared__ float sLg[32][132];
  int tid = threadIdx.x, wid = tid>>5, lane = tid&31;
  int colbase = blockIdx.x*128;
  int g = lane>>2, q = lane&3;
  float acc[2][2][4];
  #pragma unroll
  for (int m=0;m<2;m++)
    #pragma unroll
    for (int j=0;j<2;j++)
      #pragma unroll
      for (int r=0;r<4;r++) acc[m][j][r]=0.f;

  const u32* wp = d_owT + (size_t)(colbase + wid*16 + g)*512 + q;

  for (int kc=0;kc<8;kc++){
    {
      int row = tid>>3, w0 = (tid&7)*8;
      const uint4* hp = (const uint4*)(d_hbh + row*H + kc*128 + w0*2);
      *(uint4*)&sA[row][w0]   = hp[0];
      *(uint4*)&sA[row][w0+4] = hp[1];
    }
    __syncthreads();
    const u32* wkc = wp + kc*64;
    #pragma unroll
    for (int ks=0;ks<8;ks++){
      int kw = ks*8;
      u32 a00 = sA[g   ][kw+q], a10 = sA[g+8 ][kw+q];
      u32 a20 = sA[g   ][kw+4+q], a30 = sA[g+8 ][kw+4+q];
      u32 a01 = sA[g+16][kw+q], a11 = sA[g+24][kw+q];
      u32 a21 = sA[g+16][kw+4+q], a31 = sA[g+24][kw+4+q];
      #pragma unroll
      for (int j=0;j<2;j++){
        u32 b0 = wkc[j*8*512 + kw];
        u32 b1 = wkc[j*8*512 + kw + 4];
        mma_bf16(acc[0][j], a00,a10,a20,a30, b0,b1);
        mma_bf16(acc[1][j], a01,a11,a21,a31, b0,b1);
      }
    }
    __syncthreads();
  }
  #pragma unroll
  for (int m=0;m<2;m++)
    #pragma unroll
    for (int j=0;j<2;j++){
      int col = wid*16 + j*8 + q*2;
      *(float2*)&sLg[g + m*16    ][col] = make_float2(acc[m][j][0], acc[m][j][1]);
      *(float2*)&sLg[g + m*16 + 8][col] = make_float2(acc[m][j][2], acc[m][j][3]);
    }
  __syncthreads();
  const float* bp = ob + colbase;
  float4 bb = *(const float4*)(bp + lane*4);
  #pragma unroll
  for (int rr=0;rr<4;rr++){
    int b = wid*4 + rr;
    int c0 = lane*4;
    float4 v = *(float4*)&sLg[b][c0];
    v.x += bb.x; v.y += bb.y; v.z += bb.z; v.w += bb.w;
    float* orow = out + ((size_t)(b*L + t))*V + colbase;
    *(float4*)(orow + c0) = v;
    float m = v.x; int mi = c0;
    if (v.y > m){ m=v.y; mi=c0+1; }
    if (v.z > m){ m=v.z; mi=c0+2; }
    if (v.w > m){ m=v.w; mi=c0+3; }
    #pragma unroll
    for (int o=16;o>0;o>>=1){
      float om = __shfl_xor_sync(0xffffffffu, m, o);
      int   oi = __shfl_xor_sync(0xffffffffu, mi, o);
      if (om > m || (om == m && oi < mi)){ m=om; mi=oi; }
    }
    float S = expf(v.x-m)+expf(v.y-m)+expf(v.z-m)+expf(v.w-m);
    #pragma unroll
    for (int o=16;o>0;o>>=1) S += __shfl_xor_sync(0xffffffffu, S, o);
    if (lane == 0){
      d_lm2[b*250 + blockIdx.x] = m;
      d_ls2[b*250 + blockIdx.x] = S;
      d_li2[b*250 + blockIdx.x] = colbase + mi;
    }
  }
}

// ---------------- per-step: merge 250 chunk stats -> token + lse ----------------
// grid 32 (one block per batch row)
__global__ void k_tok(int t){
  __shared__ float sm[256]; __shared__ float ss[256]; __shared__ int si[256];
  int b = blockIdx.x, tid = threadIdx.x;
  float m = -INFINITY, s = 0.f; int mi = 0x7fffffff;
  for (int c = tid; c < 250; c += 256){
    float cm = d_lm2[b*250+c], cs = d_ls2[b*250+c]; int ci = d_li2[b*250+c];
    if (cm > m){ s = s*expf(m-cm) + cs; m = cm; mi = ci; }
    else { s += cs*expf(cm-m); if (cm == m && ci < mi) mi = ci; }
  }
  sm[tid]=m; ss[tid]=s; si[tid]=mi;
  __syncthreads();
  for (int st=128; st>0; st>>=1){
    if (tid < st){
      float m2 = sm[tid+st], s2 = ss[tid+st]; int i2 = si[tid+st];
      if (m2 > sm[tid]){ ss[tid] = ss[tid]*expf(sm[tid]-m2) + s2; sm[tid]=m2; si[tid]=i2; }
      else if (m2 > -INFINITY){ ss[tid] += s2*expf(m2-sm[tid]); if (m2 == sm[tid] && i2 < si[tid]) si[tid]=i2; }
    }
    __syncthreads();
  }
  if (tid == 0){
    d_tok[b] = si[0];
    d_lseA[b*L + t] = sm[0] + logf(ss[0]);
  }
}

// ---------------- final: subtract lse from every logit row ----------------
// grid 2048 (one block per (b,t) row)
__global__ void k_sub(float* __restrict__ out){
  int row = blockIdx.x;
  float lse = d_lseA[row];
  float4* p = (float4*)(out + (size_t)row*V);
  for (int i = threadIdx.x; i < V/4; i += 256){
    float4 v = p[i];
    v.x -= lse; v.y -= lse; v.z -= lse; v.w -= lse;
    p[i] = v;
  }
}

// ---------------- launcher ----------------
extern "C" void kernel_launch(void* const* d_in, const int* in_sizes, int n_in,
                              void* d_out, int out_size){
  const int*   x         = (const int*)  d_in[0];
  const float* enc_embed = (const float*)d_in[1];
  const float* enc_wx    = (const float*)d_in[2];
  const float* enc_wh    = (const float*)d_in[3];
  const float* enc_b     = (const float*)d_in[4];
  const float* dec_embed = (const float*)d_in[5];
  const float* attn_w    = (const float*)d_in[6];
  const float* attn_b    = (const float*)d_in[7];
  const float* comb_w    = (const float*)d_in[8];
  const float* comb_b    = (const float*)d_in[9];
  const float* dec_wx    = (const float*)d_in[10];
  const float* dec_wh    = (const float*)d_in[11];
  const float* dec_b     = (const float*)d_in[12];
  const float* out_w     = (const float*)d_in[13];
  const float* out_b     = (const float*)d_in[14];
  float* out = (float*)d_out;

  u32 *p_owT, *p_whT, *p_gwT, *p_cwT, *p_xwT;
  cudaGetSymbolAddress((void**)&p_owT, d_owT);
  cudaGetSymbolAddress((void**)&p_whT, d_whT);
  cudaGetSymbolAddress((void**)&p_gwT, d_gwT);
  cudaGetSymbolAddress((void**)&p_cwT, d_cwT);
  cudaGetSymbolAddress((void**)&p_xwT, d_xwT);

  k_init<<<128,256>>>();
  k_T<<<500*16,256>>>(out_w,   V,  p_owT, 512,  0,   500);  // out_w^T
  k_T<<<64*16, 256>>>(enc_wh,  G4, p_whT, 512,  0,   64);   // enc_wh^T
  k_T<<<64*16, 256>>>(dec_wx,  G4, p_gwT, 1024, 0,   64);   // dec_wx^T (K 0..1023)
  k_T<<<64*16, 256>>>(dec_wh,  G4, p_gwT, 1024, 512, 64);   // dec_wh^T (K 1024..2047)
  k_T<<<16*32, 256>>>(comb_w,  H,  p_cwT, 1024, 0,   16);   // comb_w^T
  k_T<<<64*8,  256>>>(enc_wx,  G4, p_xwT, 256,  0,   64);   // enc_wx^T
  k_xg_mma<<<2048,256>>>(x, enc_embed, enc_b);
  for (int t=0;t<64;t++){
    k_mm_bf16<<<256,256>>>(0, nullptr);           // h @ enc_wh -> gpart
    k_enc_point<<<128,256>>>(t);
  }
  k_init<<<128,256>>>();
  for (int t=0;t<64;t++){
    k_attn1<<<256,256>>>(dec_embed, attn_w);
    k_attn_ctx<<<128,256>>>(attn_b);
    k_mm_bf16<<<64,256>>>(2, dec_embed);          // concat(e,ctx) @ comb_w -> cpart
    k_combfin<<<128,256>>>(comb_b);
    k_mm_bf16<<<256,256>>>(1, nullptr);           // concat(cin,h) @ [wx;wh] -> gpart
    k_dec_point<<<128,256>>>(dec_b);
    k_logits_mma<<<250,256>>>(out_b, out, t);
    k_tok<<<32,256>>>(t);
  }
  k_sub<<<2048,256>>>(out);
}